// round 2
// baseline (speedup 1.0000x reference)
#include <cuda_runtime.h>
#include <math.h>

#define B_   1024
#define T_   200
#define E_   128
#define AH1  80
#define AH2  40
#define G_   256   // gates kept: r (0..127) and h (128..255)

typedef unsigned long long u64;

// ---------------- scratch (static device globals; no allocation) ----------------
__device__ float g_Wt[E_ * G_];                  // transposed selected w_ih: [e][g]
__device__ float g_att[B_ * T_];                 // softmax attention weights (0 on invalid t)
__device__ float g_gi[(size_t)B_ * T_ * G_];     // precomputed input gates (+b_ih)

// ---------------- helpers ----------------
__device__ __forceinline__ float sigmoidf_(float x) { return 1.0f / (1.0f + __expf(-x)); }

__device__ __forceinline__ float mytanhf_(float x) {
    float ax = fabsf(x);
    float t  = __expf(-2.0f * ax);
    float r  = (1.0f - t) / (1.0f + t);
    return copysignf(r, x);
}

// packed fp32x2 FMA (Blackwell): d.lo += a.lo*b.lo ; d.hi += a.hi*b.hi (exact fp32)
__device__ __forceinline__ void fma2_(u64 &d, u64 a, u64 b) {
    asm("fma.rn.f32x2 %0, %1, %2, %0;" : "+l"(d) : "l"(a), "l"(b));
}
__device__ __forceinline__ u64 dup2_(float x) {
    u64 r; asm("mov.b64 %0, {%1, %1};" : "=l"(r) : "f"(x)); return r;
}
__device__ __forceinline__ float2 unpack2_(u64 v) {
    float lo, hi; asm("mov.b64 {%0, %1}, %2;" : "=f"(lo), "=f"(hi) : "l"(v));
    return make_float2(lo, hi);
}

// ---------------- K0: transpose+select w_ih rows (r and h gates only) ----------------
__global__ void prep_wt_kernel(const float* __restrict__ wih) {
    int e = blockIdx.x, g = threadIdx.x;
    int row = (g < 128) ? g : g + 128;   // r gates rows 0..127; h gates rows 256..383
    g_Wt[e * G_ + g] = wih[row * E_ + e];
}

// ---------------- K1: attention MLP + masked softmax, one block per batch row --------
// dynamic SMEM layout (floats)
#define OFF_SK    0
#define OFF_SW1   (OFF_SK + 200 * 129)          // keys [200][129]
#define OFF_SH1   (OFF_SW1 + 128 * AH1)         // W_b  [128][80]
#define OFF_SW2   (OFF_SH1 + 200 * AH1)         // h1   [200][80]
#define OFF_SWD   (OFF_SW2 + AH1 * AH2)         // w2   [80][40]
#define OFF_SQA   (OFF_SWD + AH2)               // wd   [40]
#define OFF_SSC   (OFF_SQA + AH1)               // qA   [80]
#define OFF_SRED  (OFF_SSC + 200)               // scores [200]
#define OFF_QS    (OFF_SRED + 32)               // red scratch [32]
#define ATT_SMEM_FLOATS (OFF_QS + 128)          // q [128]

__global__ void __launch_bounds__(256) att_kernel(
        const float* __restrict__ qg,   const float* __restrict__ keys,
        const int* __restrict__ klen,
        const float* __restrict__ w1,   const float* __restrict__ b1,
        const float* __restrict__ w2,   const float* __restrict__ b2,
        const float* __restrict__ wd,   const float* __restrict__ bd) {
    extern __shared__ float sm[];
    float* sk   = sm + OFF_SK;
    float* sw1  = sm + OFF_SW1;
    float* sh1  = sm + OFF_SH1;
    float* sw2s = sm + OFF_SW2;
    float* swd  = sm + OFF_SWD;
    float* sqa  = sm + OFF_SQA;
    float* ssc  = sm + OFF_SSC;
    float* sred = sm + OFF_SRED;
    float* qs   = sm + OFF_QS;

    int b = blockIdx.x, tid = threadIdx.x;

    if (tid < E_) qs[tid] = qg[b * E_ + tid];
    __syncthreads();

    // fold per-batch W_b and qA in SMEM (w1 is hot in L2: 160KB total)
    for (int idx = tid; idx < E_ * AH1; idx += 256) {
        int e = idx / AH1, jj = idx - e * AH1;
        sw1[idx] = (w1[(E_ + e) * AH1 + jj] - w1[(2 * E_ + e) * AH1 + jj])
                 + qs[e] * w1[(3 * E_ + e) * AH1 + jj];
    }
    if (tid < AH1) {
        float acc = b1[tid];
        #pragma unroll 8
        for (int e = 0; e < E_; e++)
            acc += qs[e] * (w1[e * AH1 + tid] + w1[(2 * E_ + e) * AH1 + tid]);
        sqa[tid] = acc;
    }
    for (int idx = tid; idx < T_ * E_; idx += 256) {
        int t = idx >> 7, e = idx & 127;
        sk[t * 129 + e] = keys[(size_t)(b * T_ + t) * E_ + e];
    }
    for (int idx = tid; idx < AH1 * AH2; idx += 256) sw2s[idx] = w2[idx];
    if (tid < AH2) swd[tid] = wd[tid];
    __syncthreads();

    // stage1: h1[t][j] = sigmoid(qA[j] + sum_e k[t][e]*W_b[e][j]); 8t x 4j tiles, f32x2
    for (int tl = tid; tl < 500; tl += 256) {
        int t0 = (tl / 20) * 8, j0 = (tl % 20) * 4;
        ulonglong2 qav = *(const ulonglong2*)(sqa + j0);
        u64 acc2[8][2];
        #pragma unroll
        for (int i = 0; i < 8; i++) { acc2[i][0] = qav.x; acc2[i][1] = qav.y; }
        #pragma unroll 4
        for (int e = 0; e < E_; e++) {
            ulonglong2 wp = *(const ulonglong2*)(sw1 + e * AH1 + j0);
            #pragma unroll
            for (int i = 0; i < 8; i++) {
                u64 kd = dup2_(sk[(t0 + i) * 129 + e]);
                fma2_(acc2[i][0], kd, wp.x);
                fma2_(acc2[i][1], kd, wp.y);
            }
        }
        #pragma unroll
        for (int i = 0; i < 8; i++) {
            float2 p0 = unpack2_(acc2[i][0]), p1 = unpack2_(acc2[i][1]);
            sh1[(t0 + i) * AH1 + j0 + 0] = sigmoidf_(p0.x);
            sh1[(t0 + i) * AH1 + j0 + 1] = sigmoidf_(p0.y);
            sh1[(t0 + i) * AH1 + j0 + 2] = sigmoidf_(p1.x);
            sh1[(t0 + i) * AH1 + j0 + 3] = sigmoidf_(p1.y);
        }
    }
    __syncthreads();

    // stage2: h2 = sigmoid(h1 @ w2 + b2); sh2 aliases sw1 region (done with W_b)
    float* sh2 = sw1;
    for (int tl = tid; tl < 250; tl += 256) {
        int t0 = (tl / 10) * 8, j0 = (tl % 10) * 4;
        ulonglong2 bv = *(const ulonglong2*)(b2 + j0);
        u64 acc2[8][2];
        #pragma unroll
        for (int i = 0; i < 8; i++) { acc2[i][0] = bv.x; acc2[i][1] = bv.y; }
        #pragma unroll 4
        for (int e = 0; e < AH1; e++) {
            ulonglong2 wp = *(const ulonglong2*)(sw2s + e * AH2 + j0);
            #pragma unroll
            for (int i = 0; i < 8; i++) {
                u64 hd = dup2_(sh1[(t0 + i) * AH1 + e]);
                fma2_(acc2[i][0], hd, wp.x);
                fma2_(acc2[i][1], hd, wp.y);
            }
        }
        #pragma unroll
        for (int i = 0; i < 8; i++) {
            float2 p0 = unpack2_(acc2[i][0]), p1 = unpack2_(acc2[i][1]);
            sh2[(t0 + i) * AH2 + j0 + 0] = sigmoidf_(p0.x);
            sh2[(t0 + i) * AH2 + j0 + 1] = sigmoidf_(p0.y);
            sh2[(t0 + i) * AH2 + j0 + 2] = sigmoidf_(p1.x);
            sh2[(t0 + i) * AH2 + j0 + 3] = sigmoidf_(p1.y);
        }
    }
    __syncthreads();

    // stage3: scores + masked scaled softmax
    const float NEG_INF = __int_as_float(0xff800000);
    int len = klen[b];
    if (tid < T_) {
        float acc = bd[0];
        #pragma unroll 8
        for (int e = 0; e < AH2; e++) acc += sh2[tid * AH2 + e] * swd[e];
        ssc[tid] = (tid < len) ? acc * 0.08838834764831845f : NEG_INF;  // 1/sqrt(128)
    }
    __syncthreads();

    unsigned fullm = 0xffffffffu;
    float v = (tid < T_) ? ssc[tid] : NEG_INF;
    #pragma unroll
    for (int o = 16; o; o >>= 1) v = fmaxf(v, __shfl_xor_sync(fullm, v, o));
    if ((tid & 31) == 0) sred[tid >> 5] = v;
    __syncthreads();
    if (tid == 0) {
        float m = sred[0];
        #pragma unroll
        for (int k = 1; k < 8; k++) m = fmaxf(m, sred[k]);
        sred[8] = m;
    }
    __syncthreads();
    float m = sred[8];
    float ex = (tid < T_) ? __expf(ssc[tid] - m) : 0.0f;
    float s = ex;
    #pragma unroll
    for (int o = 16; o; o >>= 1) s += __shfl_xor_sync(fullm, s, o);
    if ((tid & 31) == 0) sred[16 + (tid >> 5)] = s;
    __syncthreads();
    if (tid == 0) {
        float ss = 0.0f;
        #pragma unroll
        for (int k = 0; k < 8; k++) ss += sred[16 + k];
        sred[24] = ss;
    }
    __syncthreads();
    float inv = 1.0f / sred[24];
    if (tid < T_) g_att[b * T_ + tid] = ex * inv;
}

// ---------------- K2: gi GEMM (204800 x 256) = keys (204800 x 128) @ Wt, f32x2 -------
#define GI_PAD 132
__global__ void __launch_bounds__(256) gi_kernel(const float* __restrict__ keys,
                                                 const float* __restrict__ bih) {
    __shared__ float As[32 * GI_PAD];   // [e][row], transposed keys chunk
    __shared__ float Ws[32 * GI_PAD];   // [e][g]

    int mbase = blockIdx.x * 128;
    int gbase = blockIdx.y * 128;
    int tid = threadIdx.x;
    int m0 = (tid >> 4) * 8, g0 = (tid & 15) * 8;

    u64 acc[8][4];
    #pragma unroll
    for (int i = 0; i < 8; i++)
        #pragma unroll
        for (int c = 0; c < 4; c++) acc[i][c] = 0ull;

    for (int kc = 0; kc < E_; kc += 32) {
        for (int i4 = tid; i4 < 128 * 8; i4 += 256) {
            int row = i4 >> 3, e4 = i4 & 7;
            float4 v = *(const float4*)(keys + (size_t)(mbase + row) * E_ + kc + e4 * 4);
            As[(e4 * 4 + 0) * GI_PAD + row] = v.x;
            As[(e4 * 4 + 1) * GI_PAD + row] = v.y;
            As[(e4 * 4 + 2) * GI_PAD + row] = v.z;
            As[(e4 * 4 + 3) * GI_PAD + row] = v.w;
        }
        for (int i4 = tid; i4 < 32 * 32; i4 += 256) {
            int e = i4 >> 5, g4 = i4 & 31;
            *(float4*)(Ws + e * GI_PAD + g4 * 4) =
                *(const float4*)(g_Wt + (size_t)(kc + e) * G_ + gbase + g4 * 4);
        }
        __syncthreads();

        #pragma unroll 4
        for (int e = 0; e < 32; e++) {
            float4 a0 = *(const float4*)(As + e * GI_PAD + m0);
            float4 a1 = *(const float4*)(As + e * GI_PAD + m0 + 4);
            ulonglong2 b0v = *(const ulonglong2*)(Ws + e * GI_PAD + g0);
            ulonglong2 b1v = *(const ulonglong2*)(Ws + e * GI_PAD + g0 + 4);
            float av[8] = {a0.x, a0.y, a0.z, a0.w, a1.x, a1.y, a1.z, a1.w};
            u64 bp[4] = {b0v.x, b0v.y, b1v.x, b1v.y};
            #pragma unroll
            for (int i = 0; i < 8; i++) {
                u64 ad = dup2_(av[i]);
                #pragma unroll
                for (int c = 0; c < 4; c++) fma2_(acc[i][c], ad, bp[c]);
            }
        }
        __syncthreads();
    }

    float bsel[8];
    #pragma unroll
    for (int c = 0; c < 8; c++) {
        int gg = gbase + g0 + c;
        bsel[c] = bih[(gg < 128) ? gg : gg + 128];
    }
    #pragma unroll
    for (int i = 0; i < 8; i++) {
        int mrow = mbase + m0 + i;
        float2 p0 = unpack2_(acc[i][0]), p1 = unpack2_(acc[i][1]);
        float2 p2 = unpack2_(acc[i][2]), p3 = unpack2_(acc[i][3]);
        float4 o0 = make_float4(p0.x + bsel[0], p0.y + bsel[1], p1.x + bsel[2], p1.y + bsel[3]);
        float4 o1 = make_float4(p2.x + bsel[4], p2.y + bsel[5], p3.x + bsel[6], p3.y + bsel[7]);
        *(float4*)(g_gi + (size_t)mrow * G_ + gbase + g0)     = o0;
        *(float4*)(g_gi + (size_t)mrow * G_ + gbase + g0 + 4) = o1;
    }
}

// ---------------- K3: AGRU recurrence, 8 batch rows/block, w_hh rows in registers ----
__global__ void __launch_bounds__(256, 1)
agru_kernel(const float* __restrict__ whh, const float* __restrict__ bhh,
            float* __restrict__ out) {
    __shared__ __align__(16) float hsh[8 * E_];
    __shared__ __align__(16) float rsh[8 * E_];
    __shared__ float atts[8 * T_];

    int j  = threadIdx.x;
    int b0 = blockIdx.x * 8;
    int g  = (j < 128) ? j : j + 128;      // w_hh row: r gate (0..127) or h gate (256..383)
    int j2 = j & 127;

    // 128 weights per thread as 64 packed fp32-pairs
    u64 W2[64];
    const u64* wrow = (const u64*)(whh + (size_t)g * E_);
    #pragma unroll
    for (int i = 0; i < 64; i++) W2[i] = wrow[i];
    float bh = bhh[g];

    for (int idx = j; idx < 8 * T_; idx += 256) atts[idx] = g_att[b0 * T_ + idx];
    for (int idx = j; idx < 8 * E_; idx += 256) hsh[idx] = 0.0f;
    __syncthreads();

    const float* gip = g_gi + (size_t)b0 * T_ * G_ + j;
    float gcur[8];
    #pragma unroll
    for (int r = 0; r < 8; r++) gcur[r] = gip[(size_t)r * T_ * G_];

    for (int t = 0; t < T_; t++) {
        // prefetch next-step gi (hides LDG under the matvec)
        float gnext[8];
        #pragma unroll
        for (int r = 0; r < 8; r++)
            gnext[r] = (t + 1 < T_) ? gip[(size_t)r * T_ * G_ + (size_t)(t + 1) * G_] : 0.0f;

        // matvec: gh[g] for 8 rows, f32x2 along E
        u64 acc2[8];
        #pragma unroll
        for (int r = 0; r < 8; r++) acc2[r] = 0ull;
        #pragma unroll
        for (int e4 = 0; e4 < 32; e4++) {
            #pragma unroll
            for (int r = 0; r < 8; r++) {
                ulonglong2 hv = *(const ulonglong2*)(hsh + r * E_ + e4 * 4);
                fma2_(acc2[r], W2[2 * e4],     hv.x);
                fma2_(acc2[r], W2[2 * e4 + 1], hv.y);
            }
        }

        if (j < 128) {  // r gate: r = sigmoid(i_r + h_r)
            #pragma unroll
            for (int r = 0; r < 8; r++) {
                float2 p = unpack2_(acc2[r]);
                rsh[r * E_ + j] = sigmoidf_(gcur[r] + p.x + p.y + bh);
            }
        }
        __syncthreads();
        if (j >= 128) { // h gate: new = tanh(i_h + r*h_h); h = h + a*(new-h)
            #pragma unroll
            for (int r = 0; r < 8; r++) {
                float2 p = unpack2_(acc2[r]);
                float hh = p.x + p.y + bh;
                float rv = rsh[r * E_ + j2];
                float nv = mytanhf_(gcur[r] + rv * hh);
                float a  = atts[r * T_ + t];
                float ho = hsh[r * E_ + j2];
                hsh[r * E_ + j2] = ho + a * (nv - ho);
            }
        }
        __syncthreads();
        #pragma unroll
        for (int r = 0; r < 8; r++) gcur[r] = gnext[r];
    }

    for (int idx = j; idx < 8 * E_; idx += 256)
        out[(size_t)b0 * E_ + idx] = hsh[idx];
}

// ---------------- launch ----------------
extern "C" void kernel_launch(void* const* d_in, const int* in_sizes, int n_in,
                              void* d_out, int out_size) {
    const float* qg   = (const float*)d_in[0];
    const float* keys = (const float*)d_in[1];
    const int*   klen = (const int*)d_in[2];
    const float* w1   = (const float*)d_in[3];
    const float* b1   = (const float*)d_in[4];
    const float* w2   = (const float*)d_in[5];
    const float* b2   = (const float*)d_in[6];
    const float* wd   = (const float*)d_in[7];
    const float* bd   = (const float*)d_in[8];
    const float* wih  = (const float*)d_in[9];
    const float* whh  = (const float*)d_in[10];
    const float* bih  = (const float*)d_in[11];
    const float* bhh  = (const float*)d_in[12];
    float* out = (float*)d_out;

    cudaFuncSetAttribute(att_kernel, cudaFuncAttributeMaxDynamicSharedMemorySize,
                         ATT_SMEM_FLOATS * (int)sizeof(float));

    prep_wt_kernel<<<E_, 256>>>(wih);
    att_kernel<<<B_, 256, ATT_SMEM_FLOATS * sizeof(float)>>>(qg, keys, klen, w1, b1, w2, b2, wd, bd);
    gi_kernel<<<dim3((B_ * T_) / 128, 2), 256>>>(keys, bih);
    agru_kernel<<<B_ / 8, 256>>>(whh, bhh, out);
}